// round 2
// baseline (speedup 1.0000x reference)
#include <cuda_runtime.h>
#include <cuda_bf16.h>

// RITS recurrence, persistent-CTA design:
//   grid = 128 CTAs x 256 threads, each CTA owns 2 samples for all T=512 steps.
//   W_lstm (128x256) weight-stationary in registers (thread t holds column t).
//   All other weights + activations in shared memory (~164 KB dynamic smem).
//   Inputs double-buffered (LDG one step ahead), outputs fire-and-forget STG.

#define TT 512
#define NIMP (256L * 3 * 512 * 64)

__global__ __launch_bounds__(256, 1) void rits_kernel(
    const float* __restrict__ inputs,
    const float* __restrict__ W_hist, const float* __restrict__ b_hist,
    const float* __restrict__ W_feat, const float* __restrict__ b_feat,
    const float* __restrict__ W_gx,   const float* __restrict__ b_gx,
    const float* __restrict__ W_gh,   const float* __restrict__ b_gh,
    const float* __restrict__ W_beta, const float* __restrict__ b_beta,
    const float* __restrict__ W_lstm, const float* __restrict__ U_lstm,
    const float* __restrict__ b_lstm,
    const float* __restrict__ W_out,  const float* __restrict__ b_out,
    float* __restrict__ out)
{
    extern __shared__ float sm[];
    float* sWh  = sm;            // 4096   W_hist [k*64+j]
    float* sWf  = sWh  + 4096;   // 4096   W_feat (diag zeroed)
    float* sWb  = sWf  + 4096;   // 8192   W_beta [k*64+j], k<128
    float* sWgh = sWb  + 8192;   // 4096   W_gh
    float* sU   = sWgh + 4096;   // 16384  U_lstm [k*256+o]
    float* sWgx = sU   + 16384;  // 64     diag(W_gx)
    float* sbh  = sWgx + 64;     // 64
    float* sbf  = sbh  + 64;     // 64
    float* sbgx = sbf  + 64;     // 64
    float* sbb  = sbgx + 64;     // 64
    float* sbgh = sbb  + 64;     // 64
    float* sbl  = sbgh + 64;     // 256
    float* h2    = sbl  + 256;   // 128   h[j][s]       (j*2+s)
    float* c2    = h2   + 128;   // 128   LSTM cell state
    float* hdec2 = c2   + 128;   // 128   h * gamma_h
    float* xhat2 = hdec2+ 128;   // 128
    float* xc2   = xhat2+ 128;   // 128
    float* gx2   = xc2  + 128;   // 128   gamma_x
    float* ccm2  = gx2  + 128;   // 256   [c_c ; m]
    float* zbuf  = ccm2 + 256;   // 512   LSTM pre-activations [o*2+s]
    float* pA    = zbuf + 512;   // 512   phase-A partials
    float* pz    = pA   + 512;   // 256
    float* pb    = pz   + 256;   // 512
    float* inb   = pb   + 512;   // 2 * 384  double-buffered (x,m,d)[c][j*2+s]

    const int tid = threadIdx.x;
    const int bid = blockIdx.x;

    // ---- load weights into smem / regs ----
    for (int i = tid; i < 4096; i += 256) sWh[i] = W_hist[i];
    for (int i = tid; i < 4096; i += 256) {
        int k = i >> 6, j = i & 63;
        sWf[i] = (k == j) ? 0.f : W_feat[i];
    }
    for (int i = tid; i < 8192;  i += 256) sWb[i]  = W_beta[i];
    for (int i = tid; i < 4096;  i += 256) sWgh[i] = W_gh[i];
    for (int i = tid; i < 16384; i += 256) sU[i]   = U_lstm[i];
    if (tid < 64) {
        sWgx[tid] = W_gx[tid * 64 + tid];
        sbh[tid]  = b_hist[tid];
        sbf[tid]  = b_feat[tid];
        sbgx[tid] = b_gx[tid];
        sbb[tid]  = b_beta[tid];
        sbgh[tid] = b_gh[tid];
    }
    if (tid < 256) sbl[tid] = b_lstm[tid];
    if (tid < 128) { h2[tid] = 0.f; c2[tid] = 0.f; }

    float wl[128];                      // W_lstm column `tid`, register-resident
#pragma unroll
    for (int k = 0; k < 128; k++) wl[k] = W_lstm[k * 256 + tid];

    // ---- input loader mapping (threads 0..191): (s, c, lane-pair) ----
    const int ls = tid / 96;            // sample within CTA
    const int lr = tid % 96;
    const int lc = lr / 32;             // channel: 0=x 1=m 2=d
    const int ll = lr % 32;             // lane -> 2 consecutive j
    const long lbase = ((long)(2 * bid + ls) * 3 + lc) * TT * 64;

    if (tid < 192) {
        float2 v = *(const float2*)&inputs[lbase + 2 * ll];
        inb[lc * 128 + (2 * ll)     * 2 + ls] = v.x;
        inb[lc * 128 + (2 * ll + 1) * 2 + ls] = v.y;
    }
    __syncthreads();

    // ---- phase decompositions ----
    const int g  = tid >> 7;            // phase A: 0 -> x_hat, 1 -> gamma_h pre
    const int rA = tid & 127;
    const int jA = rA & 63;
    const int kh = rA >> 6;
    const int uB = tid >> 6;            // phase B quarter
    const int jB = tid & 63;

    int p = 0;
    for (int t = 0; t < TT; t++) {
        float* bufc = inb + p * 384;

        // prefetch next step's inputs (consumed ~2000 cyc later)
        float2 pf = make_float2(0.f, 0.f);
        if (tid < 192 && t + 1 < TT)
            pf = *(const float2*)&inputs[lbase + (long)(t + 1) * 64 + 2 * ll];

        // ===== Phase A: x_hat GEMM (h @ W_hist) and gamma_h pre (d @ W_gh) =====
        {
            const float* W   = g ? sWgh : sWh;
            const float* act = g ? (bufc + 256) : h2;
            float a0 = 0.f, a1 = 0.f;
#pragma unroll
            for (int i = 0; i < 16; i++) {
                int k = kh * 32 + 2 * i;
                float4 a = *(const float4*)&act[k * 2];     // [k][s],[k+1][s]
                float w0 = W[k * 64 + jA], w1 = W[(k + 1) * 64 + jA];
                a0 += a.x * w0 + a.z * w1;
                a1 += a.y * w0 + a.w * w1;
            }
            *(float2*)&pA[(((g << 1) | kh) * 64 + jA) * 2] = make_float2(a0, a1);
        }
        __syncthreads();

        // ===== Phase A2: reduce; x_c, gamma_x, gamma_h, h_dec; write x_hat =====
        {
            int r = tid & 127, s = r & 1, j = r >> 1;
            float v = pA[g * 256 + r] + pA[g * 256 + 128 + r];
            if (g == 0) {
                float xh = v + sbh[j];
                xhat2[r] = xh;
                float x = bufc[r], m = bufc[128 + r], d = bufc[256 + r];
                xc2[r] = m * x + (1.f - m) * xh;
                gx2[r] = __expf(-fmaxf(d * sWgx[j] + sbgx[j], 0.f));
                long n = 2 * bid + s;
                out[((n * 3 + 0) * (long)TT + t) * 64 + j] = xh;
            } else {
                float gh = __expf(-fmaxf(v + sbgh[j], 0.f));
                hdec2[r] = h2[r] * gh;
            }
        }
        __syncthreads();

        // ===== Phase B: z_hat GEMM (x_c @ W_feat_c) + beta GEMM ([gx;m] @ W_beta)
        // balanced 96 MACs/thread/sample across quarters =====
        {
            float az0 = 0.f, az1 = 0.f, ab0 = 0.f, ab1 = 0.f;
            if (uB < 2) {
#pragma unroll
                for (int i = 0; i < 16; i++) {          // z_hat, 32 k
                    int k = uB * 32 + 2 * i;
                    float4 a = *(const float4*)&xc2[k * 2];
                    float w0 = sWf[k * 64 + jB], w1 = sWf[(k + 1) * 64 + jB];
                    az0 += a.x * w0 + a.z * w1;
                    az1 += a.y * w0 + a.w * w1;
                }
#pragma unroll
                for (int i = 0; i < 8; i++) {           // beta, 16 k (gamma_x)
                    int k = uB * 16 + 2 * i;
                    float4 a = *(const float4*)&gx2[k * 2];
                    float w0 = sWb[k * 64 + jB], w1 = sWb[(k + 1) * 64 + jB];
                    ab0 += a.x * w0 + a.z * w1;
                    ab1 += a.y * w0 + a.w * w1;
                }
                *(float2*)&pz[uB * 128 + jB * 2] = make_float2(az0, az1);
            } else if (uB == 2) {
#pragma unroll
                for (int i = 0; i < 16; i++) {          // beta, k 32..63 (gamma_x)
                    int k = 32 + 2 * i;
                    float4 a = *(const float4*)&gx2[k * 2];
                    float w0 = sWb[k * 64 + jB], w1 = sWb[(k + 1) * 64 + jB];
                    ab0 += a.x * w0 + a.z * w1;
                    ab1 += a.y * w0 + a.w * w1;
                }
#pragma unroll
                for (int i = 0; i < 8; i++) {           // beta, k 64..79 (m)
                    int k = 64 + 2 * i;
                    float4 a = *(const float4*)&bufc[128 + (k - 64) * 2];
                    float w0 = sWb[k * 64 + jB], w1 = sWb[(k + 1) * 64 + jB];
                    ab0 += a.x * w0 + a.z * w1;
                    ab1 += a.y * w0 + a.w * w1;
                }
            } else {
#pragma unroll
                for (int i = 0; i < 24; i++) {          // beta, k 80..127 (m)
                    int k = 80 + 2 * i;
                    float4 a = *(const float4*)&bufc[128 + (k - 64) * 2];
                    float w0 = sWb[k * 64 + jB], w1 = sWb[(k + 1) * 64 + jB];
                    ab0 += a.x * w0 + a.z * w1;
                    ab1 += a.y * w0 + a.w * w1;
                }
            }
            *(float2*)&pb[uB * 128 + jB * 2] = make_float2(ab0, ab1);
        }
        __syncthreads();

        // ===== Phase B2: z_hat, beta, c_hat, c_c; write z_hat/c_hat =====
        if (tid < 128) {
            int r = tid, s = r & 1, j = r >> 1;
            float zh   = pz[r] + pz[128 + r] + sbf[j];
            float bpre = pb[r] + pb[128 + r] + pb[256 + r] + pb[384 + r] + sbb[j];
            float beta = 1.f / (1.f + __expf(-bpre));
            float xh   = xhat2[r];
            float chat = beta * zh + (1.f - beta) * xh;
            float x = bufc[r], m = bufc[128 + r];
            float cc = m * x + (1.f - m) * chat;
            ccm2[r]       = cc;
            ccm2[128 + r] = m;
            long n = 2 * bid + s;
            out[((n * 3 + 1) * (long)TT + t) * 64 + j] = zh;
            out[((n * 3 + 2) * (long)TT + t) * 64 + j] = chat;
        }
        __syncthreads();

        // ===== Phase C: z[o] = [c_c;m] @ W_lstm (RF) + h_dec @ U (smem) + b =====
        {
            float a0 = sbl[tid], a1 = a0;
#pragma unroll
            for (int i = 0; i < 64; i++) {
                int k = 2 * i;
                float4 a = *(const float4*)&ccm2[k * 2];
                a0 += a.x * wl[k] + a.z * wl[k + 1];
                a1 += a.y * wl[k] + a.w * wl[k + 1];
            }
#pragma unroll
            for (int i = 0; i < 32; i++) {
                int k = 2 * i;
                float4 a = *(const float4*)&hdec2[k * 2];
                float u0 = sU[k * 256 + tid], u1 = sU[(k + 1) * 256 + tid];
                a0 += a.x * u0 + a.z * u1;
                a1 += a.y * u0 + a.w * u1;
            }
            *(float2*)&zbuf[tid * 2] = make_float2(a0, a1);
        }
        __syncthreads();

        // ===== Phase C2: LSTM gates; commit prefetched inputs =====
        if (tid < 128) {
            int r = tid;
            float iv = zbuf[r],       fv = zbuf[128 + r];
            float gv = zbuf[256 + r], ov = zbuf[384 + r];
            float co = c2[r];
            float si = 1.f / (1.f + __expf(-iv));
            float sf = 1.f / (1.f + __expf(-fv));
            float so = 1.f / (1.f + __expf(-ov));
            float cn = sf * co + si * tanhf(gv);
            c2[r] = cn;
            h2[r] = so * tanhf(cn);
        }
        if (tid < 192 && t + 1 < TT) {
            float* nb = inb + (p ^ 1) * 384;
            nb[lc * 128 + (2 * ll)     * 2 + ls] = pf.x;
            nb[lc * 128 + (2 * ll + 1) * 2 + ls] = pf.y;
        }
        p ^= 1;
        __syncthreads();
    }

    // ===== predictions: sigmoid(h_last @ W_out + b_out) =====
    if (tid < 64) {
        int s = tid >> 5, l = tid & 31;
        float v = h2[l * 2 + s] * W_out[l] + h2[(l + 32) * 2 + s] * W_out[l + 32];
#pragma unroll
        for (int off = 16; off; off >>= 1)
            v += __shfl_down_sync(0xffffffffu, v, off);
        if (l == 0) {
            float pv = 1.f / (1.f + __expf(-(v + b_out[0])));
            out[NIMP + 2 * bid + s] = pv;
        }
    }
}

extern "C" void kernel_launch(void* const* d_in, const int* in_sizes, int n_in,
                              void* d_out, int out_size)
{
    const float* inputs = (const float*)d_in[0];
    const float* W_hist = (const float*)d_in[1];
    const float* b_hist = (const float*)d_in[2];
    const float* W_feat = (const float*)d_in[3];
    const float* b_feat = (const float*)d_in[4];
    const float* W_gx   = (const float*)d_in[5];
    const float* b_gx   = (const float*)d_in[6];
    const float* W_gh   = (const float*)d_in[7];
    const float* b_gh   = (const float*)d_in[8];
    const float* W_beta = (const float*)d_in[9];
    const float* b_beta = (const float*)d_in[10];
    const float* W_lstm = (const float*)d_in[11];
    const float* U_lstm = (const float*)d_in[12];
    const float* b_lstm = (const float*)d_in[13];
    const float* W_out  = (const float*)d_in[14];
    const float* b_out  = (const float*)d_in[15];

    const int smem_bytes = 41088 * (int)sizeof(float);   // 164,352 B
    cudaFuncSetAttribute(rits_kernel,
                         cudaFuncAttributeMaxDynamicSharedMemorySize, smem_bytes);

    rits_kernel<<<128, 256, smem_bytes>>>(
        inputs, W_hist, b_hist, W_feat, b_feat, W_gx, b_gx, W_gh, b_gh,
        W_beta, b_beta, W_lstm, U_lstm, b_lstm, W_out, b_out,
        (float*)d_out);
}

// round 3
// speedup vs baseline: 1.1747x; 1.1747x over previous
#include <cuda_runtime.h>
#include <cuda_bf16.h>

// RITS recurrence, persistent-CTA design v2:
//  - grid 128 x 256 threads, 2 samples/CTA, full T=512 loop on-chip.
//  - W_lstm AND U_lstm weight-stationary in registers as packed f32x2 pairs
//    (192 regs/thread of weights) -> phase C has ZERO weight smem traffic.
//  - All GEMM loops use packed fma.rn.f32x2 (k-packed: no weight duplication).
//  - Activations sample-major [s][k] so packed operands come straight from
//    16B broadcast LDS; smem weights stored k-pair interleaved for LDS.64.

#define TT 512
#define NIMP (256L * 3 * 512 * 64)
typedef unsigned long long ull;

#define FMA2(acc, a, b) \
    asm("fma.rn.f32x2 %0, %1, %2, %0;" : "+l"(acc) : "l"(a), "l"(b))

__device__ __forceinline__ ull pk2(float x, float y) {
    ull r; asm("mov.b64 %0, {%1, %2};" : "=l"(r) : "f"(x), "f"(y)); return r;
}
__device__ __forceinline__ float2 upk(ull v) {
    float2 r; asm("mov.b64 {%0, %1}, %2;" : "=f"(r.x), "=f"(r.y) : "l"(v)); return r;
}

__global__ __launch_bounds__(256, 1) void rits_kernel(
    const float* __restrict__ inputs,
    const float* __restrict__ W_hist, const float* __restrict__ b_hist,
    const float* __restrict__ W_feat, const float* __restrict__ b_feat,
    const float* __restrict__ W_gx,   const float* __restrict__ b_gx,
    const float* __restrict__ W_gh,   const float* __restrict__ b_gh,
    const float* __restrict__ W_beta, const float* __restrict__ b_beta,
    const float* __restrict__ W_lstm, const float* __restrict__ U_lstm,
    const float* __restrict__ b_lstm,
    const float* __restrict__ W_out,  const float* __restrict__ b_out,
    float* __restrict__ out)
{
    extern __shared__ __align__(16) float sm[];
    float* sWh2  = sm;             // 4096  W_hist  pairs {w[2q][j],w[2q+1][j]}
    float* sWf2  = sWh2  + 4096;   // 4096  W_feat  (diag zeroed) pairs
    float* sWb2  = sWf2  + 4096;   // 8192  W_beta  pairs (q<64)
    float* sWgh2 = sWb2  + 8192;   // 4096  W_gh    pairs
    float* sWgx  = sWgh2 + 4096;   // 64    diag(W_gx)
    float* sbh   = sWgx + 64;      // 64
    float* sbf   = sbh  + 64;      // 64
    float* sbgx  = sbf  + 64;      // 64
    float* sbb   = sbgx + 64;      // 64
    float* sbgh  = sbb  + 64;      // 64
    float* sbl   = sbgh + 64;      // 256
    float* hS    = sbl  + 256;     // 128  h[s][j]
    float* cS    = hS   + 128;     // 128  cell state
    float* hdec  = cS   + 128;     // 128
    float* xhat  = hdec + 128;     // 128
    float* xc    = xhat + 128;     // 128
    float* gx    = xc   + 128;     // 128
    float* ccm   = gx   + 128;     // 256  [s][ cc(64) | m(64) ]
    float* zbuf  = ccm  + 256;     // 512  [s][o]
    float* pA    = zbuf + 512;     // 512  [(g*2+kh)][s][j]
    float* pz    = pA   + 512;     // 256  [u][s][j]  u<2
    float* pb    = pz   + 256;     // 512  [u][s][j]
    float* inb   = pb   + 512;     // 2*384 double-buffered [c][s][k]

    const int tid = threadIdx.x;
    const int bid = blockIdx.x;

    // ---- pack smem weights: {W[2q][j], W[2q+1][j]} at float offset (q*64+j)*2
    for (int i = tid; i < 2048; i += 256) {
        int q = i >> 6, j = i & 63;
        *(float2*)&sWh2[i * 2]  = make_float2(W_hist[(2*q)*64 + j], W_hist[(2*q+1)*64 + j]);
        *(float2*)&sWgh2[i * 2] = make_float2(W_gh[(2*q)*64 + j],   W_gh[(2*q+1)*64 + j]);
    }
    for (int i = tid; i < 2048; i += 256) {
        int q = i >> 6, j = i & 63;
        float a = (2*q     == j) ? 0.f : W_feat[(2*q)*64 + j];
        float b = (2*q + 1 == j) ? 0.f : W_feat[(2*q+1)*64 + j];
        *(float2*)&sWf2[i * 2] = make_float2(a, b);
    }
    for (int i = tid; i < 4096; i += 256) {
        int q = i >> 6, j = i & 63;
        *(float2*)&sWb2[i * 2] = make_float2(W_beta[(2*q)*64 + j], W_beta[(2*q+1)*64 + j]);
    }
    if (tid < 64) {
        sWgx[tid] = W_gx[tid * 64 + tid];
        sbh[tid]  = b_hist[tid];
        sbf[tid]  = b_feat[tid];
        sbgx[tid] = b_gx[tid];
        sbb[tid]  = b_beta[tid];
        sbgh[tid] = b_gh[tid];
    }
    sbl[tid] = b_lstm[tid];
    if (tid < 128) { hS[tid] = 0.f; cS[tid] = 0.f; }

    // ---- register-stationary weights: column `tid`, packed over k pairs ----
    ull wl2[64], ul2[32];
#pragma unroll
    for (int q = 0; q < 64; q++)
        wl2[q] = pk2(W_lstm[(2*q)*256 + tid], W_lstm[(2*q+1)*256 + tid]);
#pragma unroll
    for (int q = 0; q < 32; q++)
        ul2[q] = pk2(U_lstm[(2*q)*256 + tid], U_lstm[(2*q+1)*256 + tid]);

    // ---- input loader mapping (threads 0..191) ----
    const int ls = tid / 96;            // sample
    const int lr = tid % 96;
    const int lc = lr / 32;             // channel 0=x 1=m 2=d
    const int ll = lr % 32;
    const long lbase = ((long)(2 * bid + ls) * 3 + lc) * TT * 64;

    if (tid < 192) {
        float2 v = *(const float2*)&inputs[lbase + 2 * ll];
        *(float2*)&inb[lc * 128 + ls * 64 + 2 * ll] = v;
    }
    __syncthreads();

    const int g  = tid >> 7;            // phase A half
    const int kh = (tid >> 6) & 1;      // phase A k-half
    const int jA = tid & 63;
    const int u  = tid >> 6;            // phase B quarter
    const int jB = tid & 63;

    int p = 0;
    for (int t = 0; t < TT; t++) {
        float* bufc = inb + p * 384;

        float2 pf = make_float2(0.f, 0.f);
        if (tid < 192 && t + 1 < TT)
            pf = *(const float2*)&inputs[lbase + (long)(t + 1) * 64 + 2 * ll];

        // ===== Phase A: x_hat pre (h@W_hist) / gamma_h pre (d@W_gh) =====
        {
            const float* act = g ? (bufc + 256) : hS;
            const float* W   = g ? sWgh2 : sWh2;
            ull acc0 = 0, acc1 = 0;
#pragma unroll
            for (int i = 0; i < 8; i++) {
                int k = kh * 32 + 4 * i, q = k >> 1;
                ulonglong2 a0 = *(const ulonglong2*)&act[k];
                ulonglong2 a1 = *(const ulonglong2*)&act[64 + k];
                ull wa = *(const ull*)&W[(q * 64 + jA) * 2];
                ull wb = *(const ull*)&W[((q + 1) * 64 + jA) * 2];
                FMA2(acc0, wa, a0.x); FMA2(acc0, wb, a0.y);
                FMA2(acc1, wa, a1.x); FMA2(acc1, wb, a1.y);
            }
            float2 r0 = upk(acc0), r1 = upk(acc1);
            pA[(g * 2 + kh) * 128 + jA]      = r0.x + r0.y;
            pA[(g * 2 + kh) * 128 + 64 + jA] = r1.x + r1.y;
        }
        __syncthreads();

        // ===== Phase A2: x_hat, x_c, gamma_x | gamma_h, h_dec =====
        {
            int r = tid & 127, s = r >> 6, j = r & 63;
            if (g == 0) {
                float v = pA[s * 64 + j] + pA[128 + s * 64 + j] + sbh[j];
                xhat[r] = v;
                float x = bufc[r], m = bufc[128 + r], d = bufc[256 + r];
                xc[r] = m * x + (1.f - m) * v;
                gx[r] = __expf(-fmaxf(d * sWgx[j] + sbgx[j], 0.f));
                long n = 2 * bid + s;
                out[((n * 3 + 0) * (long)TT + t) * 64 + j] = v;
            } else {
                float v = pA[256 + s * 64 + j] + pA[384 + s * 64 + j];
                float gh = __expf(-fmaxf(v + sbgh[j], 0.f));
                hdec[r] = hS[r] * gh;
            }
        }
        __syncthreads();

        // ===== Phase B: z_hat (xc@W_feat_c) + beta pre ([gx;m]@W_beta) =====
        {
            ull az0 = 0, az1 = 0, ab0 = 0, ab1 = 0;
            if (u < 2) {
#pragma unroll
                for (int i = 0; i < 8; i++) {            // z_hat, 32 k
                    int k = u * 32 + 4 * i, q = k >> 1;
                    ulonglong2 a0 = *(const ulonglong2*)&xc[k];
                    ulonglong2 a1 = *(const ulonglong2*)&xc[64 + k];
                    ull wa = *(const ull*)&sWf2[(q * 64 + jB) * 2];
                    ull wb = *(const ull*)&sWf2[((q + 1) * 64 + jB) * 2];
                    FMA2(az0, wa, a0.x); FMA2(az0, wb, a0.y);
                    FMA2(az1, wa, a1.x); FMA2(az1, wb, a1.y);
                }
#pragma unroll
                for (int i = 0; i < 4; i++) {            // beta, 16 k (gamma_x)
                    int k = u * 16 + 4 * i, q = k >> 1;
                    ulonglong2 a0 = *(const ulonglong2*)&gx[k];
                    ulonglong2 a1 = *(const ulonglong2*)&gx[64 + k];
                    ull wa = *(const ull*)&sWb2[(q * 64 + jB) * 2];
                    ull wb = *(const ull*)&sWb2[((q + 1) * 64 + jB) * 2];
                    FMA2(ab0, wa, a0.x); FMA2(ab0, wb, a0.y);
                    FMA2(ab1, wa, a1.x); FMA2(ab1, wb, a1.y);
                }
                float2 r0 = upk(az0), r1 = upk(az1);
                pz[u * 128 + jB]      = r0.x + r0.y;
                pz[u * 128 + 64 + jB] = r1.x + r1.y;
            } else if (u == 2) {
#pragma unroll
                for (int i = 0; i < 8; i++) {            // beta, k 32..63 (gamma_x)
                    int k = 32 + 4 * i, q = k >> 1;
                    ulonglong2 a0 = *(const ulonglong2*)&gx[k];
                    ulonglong2 a1 = *(const ulonglong2*)&gx[64 + k];
                    ull wa = *(const ull*)&sWb2[(q * 64 + jB) * 2];
                    ull wb = *(const ull*)&sWb2[((q + 1) * 64 + jB) * 2];
                    FMA2(ab0, wa, a0.x); FMA2(ab0, wb, a0.y);
                    FMA2(ab1, wa, a1.x); FMA2(ab1, wb, a1.y);
                }
#pragma unroll
                for (int i = 0; i < 4; i++) {            // beta, k 64..79 (m)
                    int k = 64 + 4 * i, q = k >> 1;
                    ulonglong2 a0 = *(const ulonglong2*)&bufc[128 + (k - 64)];
                    ulonglong2 a1 = *(const ulonglong2*)&bufc[128 + 64 + (k - 64)];
                    ull wa = *(const ull*)&sWb2[(q * 64 + jB) * 2];
                    ull wb = *(const ull*)&sWb2[((q + 1) * 64 + jB) * 2];
                    FMA2(ab0, wa, a0.x); FMA2(ab0, wb, a0.y);
                    FMA2(ab1, wa, a1.x); FMA2(ab1, wb, a1.y);
                }
            } else {
#pragma unroll
                for (int i = 0; i < 12; i++) {           // beta, k 80..127 (m)
                    int k = 80 + 4 * i, q = k >> 1;
                    ulonglong2 a0 = *(const ulonglong2*)&bufc[128 + (k - 64)];
                    ulonglong2 a1 = *(const ulonglong2*)&bufc[128 + 64 + (k - 64)];
                    ull wa = *(const ull*)&sWb2[(q * 64 + jB) * 2];
                    ull wb = *(const ull*)&sWb2[((q + 1) * 64 + jB) * 2];
                    FMA2(ab0, wa, a0.x); FMA2(ab0, wb, a0.y);
                    FMA2(ab1, wa, a1.x); FMA2(ab1, wb, a1.y);
                }
            }
            float2 r0 = upk(ab0), r1 = upk(ab1);
            pb[u * 128 + jB]      = r0.x + r0.y;
            pb[u * 128 + 64 + jB] = r1.x + r1.y;
        }
        __syncthreads();

        // ===== Phase B2: beta, c_hat, c_c =====
        if (tid < 128) {
            int s = tid >> 6, j = tid & 63, r = tid;
            float zh   = pz[r] + pz[128 + r] + sbf[j];
            float bpre = pb[r] + pb[128 + r] + pb[256 + r] + pb[384 + r] + sbb[j];
            float beta = 1.f / (1.f + __expf(-bpre));
            float xh   = xhat[r];
            float chat = beta * zh + (1.f - beta) * xh;
            float x = bufc[r], m = bufc[128 + r];
            ccm[s * 128 + j]      = m * x + (1.f - m) * chat;
            ccm[s * 128 + 64 + j] = m;
            long n = 2 * bid + s;
            out[((n * 3 + 1) * (long)TT + t) * 64 + j] = zh;
            out[((n * 3 + 2) * (long)TT + t) * 64 + j] = chat;
        }
        __syncthreads();

        // ===== Phase C: z[o] = [c_c;m]@W_lstm (regs) + h_dec@U (regs) + b =====
        {
            ull acc0 = 0, acc1 = 0;
#pragma unroll
            for (int i = 0; i < 32; i++) {
                ulonglong2 a0 = *(const ulonglong2*)&ccm[4 * i];
                ulonglong2 a1 = *(const ulonglong2*)&ccm[128 + 4 * i];
                FMA2(acc0, wl2[2*i], a0.x); FMA2(acc0, wl2[2*i+1], a0.y);
                FMA2(acc1, wl2[2*i], a1.x); FMA2(acc1, wl2[2*i+1], a1.y);
            }
#pragma unroll
            for (int i = 0; i < 16; i++) {
                ulonglong2 a0 = *(const ulonglong2*)&hdec[4 * i];
                ulonglong2 a1 = *(const ulonglong2*)&hdec[64 + 4 * i];
                FMA2(acc0, ul2[2*i], a0.x); FMA2(acc0, ul2[2*i+1], a0.y);
                FMA2(acc1, ul2[2*i], a1.x); FMA2(acc1, ul2[2*i+1], a1.y);
            }
            float2 r0 = upk(acc0), r1 = upk(acc1);
            float b = sbl[tid];
            zbuf[tid]       = r0.x + r0.y + b;
            zbuf[256 + tid] = r1.x + r1.y + b;
        }
        __syncthreads();

        // ===== Phase C2: LSTM gates; commit prefetched inputs =====
        if (tid < 128) {
            int s = tid >> 6, j = tid & 63;
            const float* zs = zbuf + s * 256;
            float iv = zs[j], fv = zs[64 + j], gv = zs[128 + j], ov = zs[192 + j];
            float co = cS[tid];
            float si = 1.f / (1.f + __expf(-iv));
            float sf = 1.f / (1.f + __expf(-fv));
            float so = 1.f / (1.f + __expf(-ov));
            float cn = sf * co + si * tanhf(gv);
            cS[tid] = cn;
            hS[tid] = so * tanhf(cn);
        }
        if (tid < 192 && t + 1 < TT)
            *(float2*)&inb[(p ^ 1) * 384 + lc * 128 + ls * 64 + 2 * ll] = pf;
        p ^= 1;
        __syncthreads();
    }

    // ===== predictions: sigmoid(h_last @ W_out + b_out) =====
    if (tid < 64) {
        int s = tid >> 5, l = tid & 31;
        float v = hS[s * 64 + l] * W_out[l] + hS[s * 64 + 32 + l] * W_out[32 + l];
#pragma unroll
        for (int off = 16; off; off >>= 1)
            v += __shfl_down_sync(0xffffffffu, v, off);
        if (l == 0)
            out[NIMP + 2 * bid + s] = 1.f / (1.f + __expf(-(v + b_out[0])));
    }
}

extern "C" void kernel_launch(void* const* d_in, const int* in_sizes, int n_in,
                              void* d_out, int out_size)
{
    const float* inputs = (const float*)d_in[0];
    const float* W_hist = (const float*)d_in[1];
    const float* b_hist = (const float*)d_in[2];
    const float* W_feat = (const float*)d_in[3];
    const float* b_feat = (const float*)d_in[4];
    const float* W_gx   = (const float*)d_in[5];
    const float* b_gx   = (const float*)d_in[6];
    const float* W_gh   = (const float*)d_in[7];
    const float* b_gh   = (const float*)d_in[8];
    const float* W_beta = (const float*)d_in[9];
    const float* b_beta = (const float*)d_in[10];
    const float* W_lstm = (const float*)d_in[11];
    const float* U_lstm = (const float*)d_in[12];
    const float* b_lstm = (const float*)d_in[13];
    const float* W_out  = (const float*)d_in[14];
    const float* b_out  = (const float*)d_in[15];

    const int smem_bytes = 24704 * (int)sizeof(float);   // 98,816 B
    cudaFuncSetAttribute(rits_kernel,
                         cudaFuncAttributeMaxDynamicSharedMemorySize, smem_bytes);

    rits_kernel<<<128, 256, smem_bytes>>>(
        inputs, W_hist, b_hist, W_feat, b_feat, W_gx, b_gx, W_gh, b_gh,
        W_beta, b_beta, W_lstm, U_lstm, b_lstm, W_out, b_out,
        (float*)d_out);
}